// round 4
// baseline (speedup 1.0000x reference)
#include <cuda_runtime.h>

// VectorQuantizer: x (B,) int32 indices, W (K, D) fp32 codebook.
// x_emb = W[x]  =>  argmin_k ||W[x_i]-W[k]||^2 == x_i  (rows distinct; min
// inter-row distance ~2.5 >> fp noise). Therefore:
//   quantized = W[x], diff = 0, loss = 0.25 * sum(W^2).
// Output layout: [loss, quantized(B*D), diff(B*D)]  (out_size = 1 + 2*B*D).
//
// One fused kernel, three block ranges:
//   [0, SUMB)           sum(W^2); last-arriving block folds -> out[0]
//   [SUMB, SUMB+QBLK)   gather: warp-per-row, independent LDG.128s,
//                       SHFL-lane realign, STG.128 streaming stores
//   [SUMB+QBLK, GRID)   zero-fill diff, 16x STG.128/thread, streaming

#define NUM_K   8192
#define DIM     512
#define BATCH   16384
#define WSIZE   (NUM_K * DIM)          // 4194304 floats
#define BD      (BATCH * DIM)          // 8388608 floats

#define THREADS 256
#define SUMB    512                    // 512*256*8 float4 = WSIZE/4
#define QBLK    (BATCH / 8)            // 8 warps/block, 1 row/warp -> 2048
#define ZVEC    ((BD - 4) / 4)         // 2097151 float4 chunks for diff
#define ZBLK    512                    // 512*256*16 chunks >= ZVEC
#define GRID    (SUMB + QBLK + ZBLK)

__device__ float        g_partials[SUMB];
__device__ unsigned int g_count = 0;   // self-resetting ticket (graph-replay safe)

__global__ void __launch_bounds__(THREADS)
vq_fused_kernel(const int* __restrict__ x,
                const float* __restrict__ W,
                float* __restrict__ out) {
    const int blk = blockIdx.x;
    const int tid = threadIdx.x;

    if (blk < SUMB) {
        // ---- sum of squares over W: 8 front-batched float4 loads ----
        const float4* W4 = reinterpret_cast<const float4*>(W);
        size_t base = (size_t)blk * (THREADS * 8) + tid;
        float acc = 0.0f;
        #pragma unroll
        for (int i = 0; i < 8; ++i) {
            float4 v = W4[base + (size_t)i * THREADS];
            acc += v.x * v.x + v.y * v.y + v.z * v.z + v.w * v.w;
        }

        __shared__ float s[THREADS];
        s[tid] = acc;
        __syncthreads();
        #pragma unroll
        for (int o = THREADS / 2; o > 0; o >>= 1) {
            if (tid < o) s[tid] += s[tid + o];
            __syncthreads();
        }

        __shared__ bool s_last;
        if (tid == 0) {
            g_partials[blk] = s[0];
            __threadfence();
            s_last = (atomicAdd(&g_count, 1u) == SUMB - 1);
        }
        __syncthreads();

        if (s_last) {
            float p = __ldcg(&g_partials[tid]) + __ldcg(&g_partials[tid + 256]);
            s[tid] = p;
            __syncthreads();
            #pragma unroll
            for (int o = THREADS / 2; o > 0; o >>= 1) {
                if (tid < o) s[tid] += s[tid + o];
                __syncthreads();
            }
            if (tid == 0) {
                out[0] = 0.25f * s[0];
                g_count = 0;           // reset for next graph replay
            }
        }
    } else if (blk < SUMB + QBLK) {
        // ---- gather quantized = W[x]: one warp per batch row ----
        const unsigned FULL = 0xffffffffu;
        const int wid = tid >> 5;
        const int lid = tid & 31;
        const int b   = (blk - SUMB) * 8 + wid;          // batch row

        int row = 0;
        if (lid == 0) row = __ldg(&x[b]);
        row = __shfl_sync(FULL, row, 0);

        const float*  src  = W + ((size_t)row << 9);
        const float4* src4 = reinterpret_cast<const float4*>(src);
        float*        dst  = out + 1 + ((size_t)b << 9);

        // Lane 0's chunk-leading element per iteration: src[3 + 128*it].
        // Loaded directly (4 scalar LDGs on lane 0) -> iterations fully
        // independent, no cross-iteration SHFL carry chain.
        float p0 = 0.f, p1 = 0.f, p2 = 0.f, p3 = 0.f;
        if (lid == 0) {
            p0 = __ldg(src + 3);
            p1 = __ldg(src + 131);
            p2 = __ldg(src + 259);
            p3 = __ldg(src + 387);
        }

        // 127 aligned output chunks: dst[3+4k .. 7+4k) = (src[3+4k], src4[k+1].xyz)
        #pragma unroll
        for (int it = 0; it < 4; ++it) {
            int  k  = it * 32 + lid;
            int  kc = (k < 127) ? k : 126;               // clamp OOB lane
            float4 A = src4[kc + 1];                     // aligned LDG.128
            float wprev = __shfl_up_sync(FULL, A.w, 1);
            float pb = (it == 0) ? p0 : (it == 1) ? p1 : (it == 2) ? p2 : p3;
            float vx = (lid == 0) ? pb : wprev;
            if (k < 127) {
                float4 v = make_float4(vx, A.x, A.y, A.z);
                __stcs(reinterpret_cast<float4*>(dst + 3 + 4 * k), v);
            }
        }

        // edges: dst[0..2] = src[0..2], dst[511] = src[511]
        if (lid < 3)       dst[lid] = __ldg(src + lid);
        else if (lid == 3) dst[511] = __ldg(src + 511);

        // global scalar edges of the diff region (done once)
        if (blk == SUMB && wid == 0 && lid < 4) {
            size_t idx = (lid < 3) ? ((size_t)BD + 1 + lid) : (size_t)2 * BD;
            out[idx] = 0.0f;
        }
    } else {
        // ---- diff zero-fill: 16 streaming STG.128 per thread ----
        float4 z = make_float4(0.f, 0.f, 0.f, 0.f);
        int t0 = (blk - SUMB - QBLK) * THREADS + tid;
        float* zbase = out + 4 + (size_t)BD;
        #pragma unroll
        for (int i = 0; i < 16; ++i) {
            int t = t0 + i * (ZBLK * THREADS);
            if (t < ZVEC)
                __stcs(reinterpret_cast<float4*>(zbase + (size_t)4 * t), z);
        }
    }
}

extern "C" void kernel_launch(void* const* d_in, const int* in_sizes, int n_in,
                              void* d_out, int out_size) {
    const int*   x = nullptr;
    const float* W = nullptr;
    if (in_sizes[0] == BATCH) {
        x = (const int*)d_in[0];
        W = (const float*)d_in[1];
    } else {
        W = (const float*)d_in[0];
        x = (const int*)d_in[1];
    }
    float* out = (float*)d_out;
    vq_fused_kernel<<<GRID, THREADS>>>(x, W, out);
}